// round 2
// baseline (speedup 1.0000x reference)
#include <cuda_runtime.h>
#include <math.h>
#include <stdint.h>

#define NN 100000
#define EE 800000
#define GG 256
#define HCC 128
#define EDIMC 16
#define SLOPE 0.2f
#define BN_EPS 1e-5f
#define ENC_NEGINF 0x007FFFFFu

// ---------------- scratch (device globals; no allocations) ----------------
__device__ __align__(16) float    g_A[(size_t)NN * HCC];   // xl (post-GEMM features)
__device__ __align__(16) float    g_B[(size_t)NN * HCC];   // layer output / next input
__device__ __align__(16) float    g_alpha[(size_t)EE * 4];
__device__ __align__(16) float    g_asrc[NN * 4];
__device__ __align__(16) float    g_adst[NN * 4];
__device__ __align__(16) unsigned g_amax[NN * 4];
__device__ __align__(16) float    g_denom[NN * 4];
__device__ double g_bnsum[HCC];
__device__ double g_bnsq[HCC];
__device__ float  g_M2[3 * EDIMC * 4];
__device__ float  g_c2[3 * 4];
__device__ __align__(16) float g_pool[GG * HCC];
__device__ float g_cnt[GG];
__device__ int   g_src[EE];
__device__ int   g_dst[EE];
__device__ int   g_batch[NN];
__device__ int   g_is64;

// orderable float encoding for atomicMax
__device__ __forceinline__ unsigned encf(float f) {
    unsigned u = __float_as_uint(f);
    return (u & 0x80000000u) ? ~u : (u | 0x80000000u);
}
__device__ __forceinline__ float decf(unsigned u) {
    return (u & 0x80000000u) ? __uint_as_float(u & 0x7fffffffu)
                             : __uint_as_float(~u);
}

// ---------------- dtype detection (int64 vs int32 indices) ----------------
__global__ void k_detect(const int* __restrict__ ei_raw) {
    if (threadIdx.x == 0) {
        int ok = 1;
        for (int i = 0; i < 64; i++)
            if (ei_raw[2 * i + 1] != 0) ok = 0;
        g_is64 = ok;
    }
}

__global__ void k_init_pool() {
    int i = blockIdx.x * blockDim.x + threadIdx.x;
    if (i < GG * HCC) g_pool[i] = 0.f;
    if (i < GG) g_cnt[i] = 0.f;
}

__global__ void k_prep(const void* __restrict__ ei_raw,
                       const void* __restrict__ batch_raw) {
    int i = blockIdx.x * blockDim.x + threadIdx.x;
    int is64 = g_is64;
    if (i < EE) {
        int s, d;
        if (is64) {
            const long long* p = (const long long*)ei_raw;
            s = (int)p[i]; d = (int)p[EE + i];
        } else {
            const int* p = (const int*)ei_raw;
            s = p[i]; d = p[EE + i];
        }
        g_src[i] = s; g_dst[i] = d;
    }
    if (i < NN) {
        int b = is64 ? (int)((const long long*)batch_raw)[i]
                     : ((const int*)batch_raw)[i];
        g_batch[i] = b;
        atomicAdd(&g_cnt[b], 1.0f);
    }
}

// M2[l][k16][h] = sum_{k32,c} efW[k16,k32] * lin_e[l,k32,h*32+c] * att_e[l,h,c]
// c2[l][h]     = sum_{k32,c} efb[k32]      * lin_e[l,k32,h*32+c] * att_e[l,h,c]
__global__ void k_m2(const float* __restrict__ lin_e,
                     const float* __restrict__ att_e,
                     const float* __restrict__ efW,
                     const float* __restrict__ efb) {
    int idx = threadIdx.x;
    if (idx < 3 * EDIMC * 4) {
        int l = idx / (EDIMC * 4), r = idx % (EDIMC * 4);
        int k16 = r / 4, h = r % 4;
        float t = 0.f;
        for (int k32 = 0; k32 < 32; k32++) {
            float m = 0.f;
            const float* le = lin_e + (size_t)l * 32 * HCC + k32 * HCC + h * 32;
            const float* ae = att_e + l * HCC + h * 32;
            for (int c = 0; c < 32; c++) m += le[c] * ae[c];
            t += efW[k16 * 32 + k32] * m;
        }
        g_M2[l * (EDIMC * 4) + k16 * 4 + h] = t;
    } else if (idx < 3 * EDIMC * 4 + 12) {
        int j = idx - 3 * EDIMC * 4;
        int l = j / 4, h = j % 4;
        float t = 0.f;
        for (int k32 = 0; k32 < 32; k32++) {
            float m = 0.f;
            const float* le = lin_e + (size_t)l * 32 * HCC + k32 * HCC + h * 32;
            const float* ae = att_e + l * HCC + h * 32;
            for (int c = 0; c < 32; c++) m += le[c] * ae[c];
            t += efb[k32] * m;
        }
        g_c2[l * 4 + h] = t;
    }
}

// ---------------- GEMM: g_A = hin @ W, hin = x (layer 0) or g_B ----------
__global__ void k_gemm(const float* __restrict__ x_in, int use_x,
                       const float* __restrict__ W) {
    __shared__ float sW[32][HCC];   // 16 KB
    __shared__ float sA[64][36];    // padded, 9 KB
    const float* A = use_x ? x_in : g_B;
    int row0 = blockIdx.x * 64;
    int tid = threadIdx.x;
    int tx = tid & 15, ty = tid >> 4;
    int m0 = ty * 4, c0 = tx * 8;
    float acc[4][8];
#pragma unroll
    for (int i = 0; i < 4; i++)
#pragma unroll
        for (int j = 0; j < 8; j++) acc[i][j] = 0.f;

    for (int kc = 0; kc < 4; kc++) {
        int k0 = kc * 32;
#pragma unroll
        for (int t = tid; t < 1024; t += 256) {
            int k = t >> 5, c4 = t & 31;
            ((float4*)&sW[k][0])[c4] =
                ((const float4*)(W + (size_t)(k0 + k) * HCC))[c4];
        }
#pragma unroll
        for (int t = tid; t < 512; t += 256) {
            int m = t >> 3, k4 = t & 7;
            int r = row0 + m;
            float4 v = (r < NN)
                ? ((const float4*)(A + (size_t)r * HCC))[kc * 8 + k4]
                : make_float4(0.f, 0.f, 0.f, 0.f);
            *(float4*)&sA[m][k4 * 4] = v;
        }
        __syncthreads();
#pragma unroll
        for (int k = 0; k < 32; k++) {
            float aa[4];
            aa[0] = sA[m0 + 0][k]; aa[1] = sA[m0 + 1][k];
            aa[2] = sA[m0 + 2][k]; aa[3] = sA[m0 + 3][k];
            float4 b0 = *(float4*)&sW[k][c0];
            float4 b1 = *(float4*)&sW[k][c0 + 4];
            float bb[8] = {b0.x, b0.y, b0.z, b0.w, b1.x, b1.y, b1.z, b1.w};
#pragma unroll
            for (int i = 0; i < 4; i++)
#pragma unroll
                for (int j = 0; j < 8; j++) acc[i][j] += aa[i] * bb[j];
        }
        __syncthreads();
    }
#pragma unroll
    for (int i = 0; i < 4; i++) {
        int r = row0 + m0 + i;
        if (r < NN) {
            float4 o0 = {acc[i][0], acc[i][1], acc[i][2], acc[i][3]};
            float4 o1 = {acc[i][4], acc[i][5], acc[i][6], acc[i][7]};
            float4* Cr = (float4*)(g_A + (size_t)r * HCC);
            Cr[tx * 2] = o0;
            Cr[tx * 2 + 1] = o1;
        }
    }
}

// ---------------- per-node attention dot products ------------------------
__global__ void k_attnvec(const float* __restrict__ asl,
                          const float* __restrict__ adl) {
    int warp = (blockIdx.x * blockDim.x + threadIdx.x) >> 5;
    int lane = threadIdx.x & 31;
    if (warp >= NN) return;
    int h = lane >> 3, part = lane & 7;
    float4 v = ((const float4*)(g_A + (size_t)warp * HCC))[lane];
    float4 a = ((const float4*)asl)[h * 8 + part];
    float4 b = ((const float4*)adl)[h * 8 + part];
    float ps = v.x * a.x + v.y * a.y + v.z * a.z + v.w * a.w;
    float pd = v.x * b.x + v.y * b.y + v.z * b.z + v.w * b.w;
#pragma unroll
    for (int off = 4; off > 0; off >>= 1) {
        ps += __shfl_down_sync(0xffffffffu, ps, off, 8);
        pd += __shfl_down_sync(0xffffffffu, pd, off, 8);
    }
    if (part == 0) {
        g_asrc[warp * 4 + h] = ps;
        g_adst[warp * 4 + h] = pd;
    }
}

__global__ void k_init_layer() {
    int i = blockIdx.x * blockDim.x + threadIdx.x;
    if (i < NN * HCC) g_B[i] = 0.f;
    if (i < NN * 4) { g_amax[i] = ENC_NEGINF; g_denom[i] = 0.f; }
    if (i < HCC) { g_bnsum[i] = 0.0; g_bnsq[i] = 0.0; }
}

// ---------------- alpha + running max ------------------------------------
__global__ void k_alpha(const float* __restrict__ ea, int l) {
    __shared__ float sM[EDIMC * 4];
    __shared__ float sc[4];
    if (threadIdx.x < EDIMC * 4) sM[threadIdx.x] = g_M2[l * EDIMC * 4 + threadIdx.x];
    if (threadIdx.x < 4) sc[threadIdx.x] = g_c2[l * 4 + threadIdx.x];
    __syncthreads();
    int e = blockIdx.x * blockDim.x + threadIdx.x;
    if (e >= EE) return;
    int s = g_src[e], d = g_dst[e];
    float4 as = ((const float4*)g_asrc)[s];
    float4 ad = ((const float4*)g_adst)[d];
    float ev[EDIMC];
    const float4* ep = (const float4*)(ea + (size_t)e * EDIMC);
#pragma unroll
    for (int q = 0; q < 4; q++) {
        float4 v = ep[q];
        ev[q * 4 + 0] = v.x; ev[q * 4 + 1] = v.y;
        ev[q * 4 + 2] = v.z; ev[q * 4 + 3] = v.w;
    }
    float base[4] = {as.x + ad.x, as.y + ad.y, as.z + ad.z, as.w + ad.w};
    float out[4];
#pragma unroll
    for (int h = 0; h < 4; h++) {
        float t = sc[h];
#pragma unroll
        for (int k = 0; k < EDIMC; k++) t += ev[k] * sM[k * 4 + h];
        float al = base[h] + t;
        al = (al > 0.f) ? al : SLOPE * al;
        out[h] = al;
        atomicMax(&g_amax[d * 4 + h], encf(al));
    }
    ((float4*)g_alpha)[e] = make_float4(out[0], out[1], out[2], out[3]);
}

// ---------------- exp + denominator --------------------------------------
__global__ void k_exp() {
    int e = blockIdx.x * blockDim.x + threadIdx.x;
    if (e >= EE) return;
    int d = g_dst[e];
    float4 a = ((const float4*)g_alpha)[e];
    uint4 m = ((const uint4*)g_amax)[d];
    float4 r;
    r.x = expf(a.x - decf(m.x));
    r.y = expf(a.y - decf(m.y));
    r.z = expf(a.z - decf(m.z));
    r.w = expf(a.w - decf(m.w));
    ((float4*)g_alpha)[e] = r;
    atomicAdd(((float4*)g_denom) + d, r);
}

// ---------------- weighted scatter-aggregate (warp per edge) -------------
__global__ void k_agg() {
    int gid = blockIdx.x * blockDim.x + threadIdx.x;
    int e = gid >> 5;
    int lane = threadIdx.x & 31;
    if (e >= EE) return;
    int s = g_src[e], d = g_dst[e];
    int h = lane >> 3;
    float coef = g_alpha[(size_t)e * 4 + h] / (g_denom[d * 4 + h] + 1e-16f);
    float4 v = ((const float4*)(g_A + (size_t)s * HCC))[lane];
    float4 r = make_float4(coef * v.x, coef * v.y, coef * v.z, coef * v.w);
    atomicAdd(((float4*)(g_B + (size_t)d * HCC)) + lane, r);
}

// ---------------- batch-norm stats ---------------------------------------
__global__ void k_bnstat() {
    int c = threadIdx.x;  // 128 threads
    double s = 0.0, q = 0.0;
    for (int r = blockIdx.x; r < NN; r += gridDim.x) {
        float v = g_B[(size_t)r * HCC + c];
        s += v;
        q += (double)v * v;
    }
    atomicAdd(&g_bnsum[c], s);
    atomicAdd(&g_bnsq[c], q);
}

__global__ void k_bnapply(const float* __restrict__ gamma,
                          const float* __restrict__ beta) {
    int i = blockIdx.x * blockDim.x + threadIdx.x;
    if (i >= NN * HCC) return;
    int c = i & (HCC - 1);
    float mu = (float)(g_bnsum[c] / (double)NN);
    float var = (float)(g_bnsq[c] / (double)NN) - mu * mu;
    float rstd = rsqrtf(var + BN_EPS);
    float v = g_B[i];
    v = (v - mu) * rstd * gamma[c] + beta[c];
    g_B[i] = (v > 0.f) ? v : 0.f;
}

// ---------------- pooling + final FC --------------------------------------
__global__ void k_pool() {
    int i = blockIdx.x * blockDim.x + threadIdx.x;
    if (i >= NN * 32) return;
    int n = i >> 5, q = i & 31;
    int g = g_batch[n];
    float4 v = ((const float4*)(g_B + (size_t)n * HCC))[q];
    atomicAdd(((float4*)(g_pool + (size_t)g * HCC)) + q, v);
}

__global__ void k_fc(const float* __restrict__ fcW,
                     const float* __restrict__ fcb,
                     float* __restrict__ out) {
    int g = threadIdx.x;
    if (g >= GG) return;
    float inv = 1.f / fmaxf(g_cnt[g], 1.f);
    float o0 = fcb[0], o1 = fcb[1];
    for (int c = 0; c < HCC; c++) {
        float p = g_pool[(size_t)g * HCC + c] * inv;
        o0 += p * fcW[c * 2 + 0];
        o1 += p * fcW[c * 2 + 1];
    }
    out[g * 2 + 0] = o0;
    out[g * 2 + 1] = o1;
}

// ---------------- launch ---------------------------------------------------
extern "C" void kernel_launch(void* const* d_in, const int* in_sizes, int n_in,
                              void* d_out, int out_size) {
    const float* x     = (const float*)d_in[0];
    const void*  ei    = d_in[1];
    const float* ea    = (const float*)d_in[2];
    const void*  batch = d_in[3];
    const float* efW   = (const float*)d_in[4];
    const float* efb   = (const float*)d_in[5];
    const float* Ws    = (const float*)d_in[6];
    const float* a_s   = (const float*)d_in[7];
    const float* a_d   = (const float*)d_in[8];
    const float* a_e   = (const float*)d_in[9];
    const float* lin_e = (const float*)d_in[10];
    const float* gamma = (const float*)d_in[12];
    const float* beta  = (const float*)d_in[13];
    const float* fcW   = (const float*)d_in[14];
    const float* fcb   = (const float*)d_in[15];
    float* out = (float*)d_out;

    k_detect<<<1, 32>>>((const int*)ei);
    k_init_pool<<<(GG * HCC + 255) / 256, 256>>>();
    k_prep<<<(EE + 255) / 256, 256>>>(ei, batch);
    k_m2<<<1, 256>>>(lin_e, a_e, efW, efb);

    for (int l = 0; l < 3; l++) {
        k_gemm<<<(NN + 63) / 64, 256>>>(x, (l == 0) ? 1 : 0,
                                        Ws + (size_t)l * HCC * HCC);
        k_attnvec<<<(NN * 32 + 255) / 256, 256>>>(a_s + l * HCC, a_d + l * HCC);
        k_init_layer<<<(NN * HCC + 255) / 256, 256>>>();
        k_alpha<<<(EE + 255) / 256, 256>>>(ea, l);
        k_exp<<<(EE + 255) / 256, 256>>>();
        k_agg<<<(EE * 32 + 255) / 256, 256>>>();
        k_bnstat<<<512, 128>>>();
        k_bnapply<<<(NN * HCC + 255) / 256, 256>>>(gamma + l * HCC,
                                                   beta + l * HCC);
    }

    k_pool<<<(NN * 32 + 255) / 256, 256>>>();
    k_fc<<<1, 256>>>(fcW, fcb, out);
}

// round 5
// speedup vs baseline: 2.1964x; 2.1964x over previous
#include <cuda_runtime.h>
#include <math.h>
#include <stdint.h>

#define NN 100000
#define EE 800000
#define GG 256
#define HCC 128
#define EDIMC 16
#define SLOPE 0.2f
#define BN_EPS 1e-5f

// ---------------- scratch (device globals; no allocations) ----------------
__device__ __align__(16) float g_A[(size_t)NN * HCC];    // xl (post-GEMM features)
__device__ __align__(16) float g_B[(size_t)NN * HCC];    // aggregated output (raw, pre-BN)
__device__ __align__(16) float g_alpha[(size_t)EE * 4];  // exp(alpha)
__device__ __align__(16) float g_e2[(size_t)3 * EE * 4]; // per-layer edge attn term
__device__ __align__(16) float g_asrc[NN * 4];
__device__ __align__(16) float g_adst[NN * 4];
__device__ __align__(16) float g_denom[NN * 4];
__device__ double g_bnsum[HCC];
__device__ double g_bnsq[HCC];
__device__ float  g_bnscale[HCC];
__device__ float  g_bnshift[HCC];
__device__ float  g_M2[3 * EDIMC * 4];
__device__ float  g_c2[3 * 4];
__device__ __align__(16) float g_pool[GG * HCC];
__device__ float g_cnt[GG];
__device__ int   g_src[EE];
__device__ int   g_dst[EE];
__device__ int   g_batch[NN];
__device__ int   g_is64;

// ---------------- dtype detection (int64 vs int32 indices) ----------------
__global__ void k_detect(const int* __restrict__ ei_raw) {
    if (threadIdx.x == 0) {
        int ok = 1;
        for (int i = 0; i < 64; i++)
            if (ei_raw[2 * i + 1] != 0) ok = 0;
        g_is64 = ok;
    }
}

__global__ void k_init_pool() {
    int i = blockIdx.x * blockDim.x + threadIdx.x;
    if (i < GG * HCC) g_pool[i] = 0.f;
    if (i < GG) g_cnt[i] = 0.f;
}

__global__ void k_prep(const void* __restrict__ ei_raw,
                       const void* __restrict__ batch_raw) {
    int i = blockIdx.x * blockDim.x + threadIdx.x;
    int is64 = g_is64;
    if (i < EE) {
        int s, d;
        if (is64) {
            const long long* p = (const long long*)ei_raw;
            s = (int)p[i]; d = (int)p[EE + i];
        } else {
            const int* p = (const int*)ei_raw;
            s = p[i]; d = p[EE + i];
        }
        g_src[i] = s; g_dst[i] = d;
    }
    if (i < NN) {
        int b = is64 ? (int)((const long long*)batch_raw)[i]
                     : ((const int*)batch_raw)[i];
        g_batch[i] = b;
        atomicAdd(&g_cnt[b], 1.0f);
    }
}

// ---------------- M2 fold: warp per output --------------------------------
__global__ void k_m2(const float* __restrict__ lin_e,
                     const float* __restrict__ att_e,
                     const float* __restrict__ efW,
                     const float* __restrict__ efb) {
    int out = blockIdx.x;
    int lane = threadIdx.x;
    float t = 0.f;
    if (out < 3 * EDIMC * 4) {
        int l = out / (EDIMC * 4), r = out % (EDIMC * 4);
        int k16 = r / 4, h = r % 4;
        for (int idx = lane; idx < 32 * 32; idx += 32) {
            int k32 = idx >> 5, c = idx & 31;
            t += efW[k16 * 32 + k32] *
                 lin_e[(size_t)l * 32 * HCC + k32 * HCC + h * 32 + c] *
                 att_e[l * HCC + h * 32 + c];
        }
#pragma unroll
        for (int off = 16; off > 0; off >>= 1)
            t += __shfl_down_sync(0xffffffffu, t, off);
        if (lane == 0) g_M2[l * (EDIMC * 4) + k16 * 4 + h] = t;
    } else {
        int j = out - 3 * EDIMC * 4;
        if (j >= 12) return;
        int l = j / 4, h = j % 4;
        for (int idx = lane; idx < 32 * 32; idx += 32) {
            int k32 = idx >> 5, c = idx & 31;
            t += efb[k32] *
                 lin_e[(size_t)l * 32 * HCC + k32 * HCC + h * 32 + c] *
                 att_e[l * HCC + h * 32 + c];
        }
#pragma unroll
        for (int off = 16; off > 0; off >>= 1)
            t += __shfl_down_sync(0xffffffffu, t, off);
        if (lane == 0) g_c2[l * 4 + h] = t;
    }
}

// ---------------- edge term for all 3 layers in one pass ------------------
__global__ void k_e2(const float* __restrict__ ea) {
    __shared__ float sM[3 * EDIMC * 4];
    __shared__ float sc[12];
    if (threadIdx.x < 3 * EDIMC * 4) sM[threadIdx.x] = g_M2[threadIdx.x];
    if (threadIdx.x < 12) sc[threadIdx.x] = g_c2[threadIdx.x];
    __syncthreads();
    int e = blockIdx.x * blockDim.x + threadIdx.x;
    if (e >= EE) return;
    float ev[EDIMC];
    const float4* ep = (const float4*)(ea + (size_t)e * EDIMC);
#pragma unroll
    for (int q = 0; q < 4; q++) {
        float4 v = ep[q];
        ev[q * 4 + 0] = v.x; ev[q * 4 + 1] = v.y;
        ev[q * 4 + 2] = v.z; ev[q * 4 + 3] = v.w;
    }
#pragma unroll
    for (int l = 0; l < 3; l++) {
        float o[4];
#pragma unroll
        for (int h = 0; h < 4; h++) {
            float t = sc[l * 4 + h];
#pragma unroll
            for (int k = 0; k < EDIMC; k++)
                t += ev[k] * sM[l * 64 + k * 4 + h];
            o[h] = t;
        }
        ((float4*)g_e2)[(size_t)l * EE + e] = make_float4(o[0], o[1], o[2], o[3]);
    }
}

// ---------------- fused GEMM (+BN-on-load, +attn-dot epilogue) -------------
// input selected DEVICE-SIDE: use_x ? x_in : g_B   (never pass g_B from host!)
__global__ __launch_bounds__(256, 2)
void k_gemm(const float* __restrict__ x_in, int use_x, int apply_bn,
            const float* __restrict__ W,
            const float* __restrict__ asl,
            const float* __restrict__ adl) {
    __shared__ float sA[16][132];
    __shared__ float sW[16][128];
    __shared__ float sAs[128], sAd[128];
    __shared__ float sScale[128], sShift[128];

    const float* A = use_x ? x_in : (const float*)g_B;

    int tid = threadIdx.x;
    int tx = tid & 15, ty = tid >> 4;
    int m0 = ty * 8, n0 = tx * 8;
    int row0 = blockIdx.x * 128;

    if (tid < 128) {
        sAs[tid] = asl[tid];
        sAd[tid] = adl[tid];
        if (apply_bn) {
            sScale[tid] = g_bnscale[tid];
            sShift[tid] = g_bnshift[tid];
        }
    }
    __syncthreads();

    float acc[8][8];
#pragma unroll
    for (int i = 0; i < 8; i++)
#pragma unroll
        for (int j = 0; j < 8; j++) acc[i][j] = 0.f;

    for (int kc = 0; kc < 8; kc++) {
        int k0 = kc * 16;
#pragma unroll
        for (int t = tid; t < 512; t += 256) {
            int k = t >> 5, c = t & 31;
            ((float4*)&sW[k][0])[c] =
                ((const float4*)(W + (size_t)(k0 + k) * HCC))[c];
        }
#pragma unroll
        for (int t = tid; t < 512; t += 256) {
            int r = t >> 2, q = t & 3;
            int gr = row0 + r;
            float4 v = (gr < NN)
                ? ((const float4*)(A + (size_t)gr * HCC))[kc * 4 + q]
                : make_float4(0.f, 0.f, 0.f, 0.f);
            if (apply_bn) {
                int c = k0 + q * 4;
                v.x = fmaxf(v.x * sScale[c + 0] + sShift[c + 0], 0.f);
                v.y = fmaxf(v.y * sScale[c + 1] + sShift[c + 1], 0.f);
                v.z = fmaxf(v.z * sScale[c + 2] + sShift[c + 2], 0.f);
                v.w = fmaxf(v.w * sScale[c + 3] + sShift[c + 3], 0.f);
            }
            sA[q * 4 + 0][r] = v.x;
            sA[q * 4 + 1][r] = v.y;
            sA[q * 4 + 2][r] = v.z;
            sA[q * 4 + 3][r] = v.w;
        }
        __syncthreads();
#pragma unroll
        for (int k = 0; k < 16; k++) {
            float4 a0 = *(float4*)&sA[k][m0];
            float4 a1 = *(float4*)&sA[k][m0 + 4];
            float4 b0 = *(float4*)&sW[k][n0];
            float4 b1 = *(float4*)&sW[k][n0 + 4];
            float aa[8] = {a0.x, a0.y, a0.z, a0.w, a1.x, a1.y, a1.z, a1.w};
            float bb[8] = {b0.x, b0.y, b0.z, b0.w, b1.x, b1.y, b1.z, b1.w};
#pragma unroll
            for (int i = 0; i < 8; i++)
#pragma unroll
                for (int j = 0; j < 8; j++)
                    acc[i][j] += aa[i] * bb[j];
        }
        __syncthreads();
    }

    // epilogue: store C + attention dots (reduce over 4 lanes = one head)
    int h = tx >> 2;
#pragma unroll
    for (int i = 0; i < 8; i++) {
        int r = row0 + m0 + i;
        float ps = 0.f, pd = 0.f;
#pragma unroll
        for (int j = 0; j < 8; j++) {
            ps += acc[i][j] * sAs[n0 + j];
            pd += acc[i][j] * sAd[n0 + j];
        }
#pragma unroll
        for (int off = 1; off < 4; off <<= 1) {
            ps += __shfl_xor_sync(0xffffffffu, ps, off, 4);
            pd += __shfl_xor_sync(0xffffffffu, pd, off, 4);
        }
        if (r < NN) {
            float4 o0 = {acc[i][0], acc[i][1], acc[i][2], acc[i][3]};
            float4 o1 = {acc[i][4], acc[i][5], acc[i][6], acc[i][7]};
            float4* Cr = (float4*)(g_A + (size_t)r * HCC);
            Cr[tx * 2] = o0;
            Cr[tx * 2 + 1] = o1;
            if ((tx & 3) == 0) {
                g_asrc[r * 4 + h] = ps;
                g_adst[r * 4 + h] = pd;
            }
        }
    }
}

__global__ void k_init_layer() {
    int i = blockIdx.x * blockDim.x + threadIdx.x;
    if (i < NN * HCC) g_B[i] = 0.f;
    if (i < NN * 4) g_denom[i] = 0.f;
    if (i < HCC) { g_bnsum[i] = 0.0; g_bnsq[i] = 0.0; }
}

// ---------------- fused alpha + leaky + exp + denom -----------------------
__global__ void k_alphaexp(int l) {
    int e = blockIdx.x * blockDim.x + threadIdx.x;
    if (e >= EE) return;
    int s = g_src[e], d = g_dst[e];
    float4 as = ((const float4*)g_asrc)[s];
    float4 ad = ((const float4*)g_adst)[d];
    float4 e2 = ((const float4*)g_e2)[(size_t)l * EE + e];
    float a0 = as.x + ad.x + e2.x;
    float a1 = as.y + ad.y + e2.y;
    float a2 = as.z + ad.z + e2.z;
    float a3 = as.w + ad.w + e2.w;
    a0 = (a0 > 0.f) ? a0 : SLOPE * a0;
    a1 = (a1 > 0.f) ? a1 : SLOPE * a1;
    a2 = (a2 > 0.f) ? a2 : SLOPE * a2;
    a3 = (a3 > 0.f) ? a3 : SLOPE * a3;
    float4 w = make_float4(__expf(a0), __expf(a1), __expf(a2), __expf(a3));
    ((float4*)g_alpha)[e] = w;
    atomicAdd(((float4*)g_denom) + d, w);
}

// ---------------- weighted scatter-aggregate (warp per edge) --------------
__global__ void k_agg() {
    int gid = blockIdx.x * blockDim.x + threadIdx.x;
    int e = gid >> 5;
    int lane = threadIdx.x & 31;
    if (e >= EE) return;
    int s = g_src[e], d = g_dst[e];
    int h = lane >> 3;
    float coef = g_alpha[(size_t)e * 4 + h] / (g_denom[d * 4 + h] + 1e-16f);
    float4 v = ((const float4*)(g_A + (size_t)s * HCC))[lane];
    float4 r = make_float4(coef * v.x, coef * v.y, coef * v.z, coef * v.w);
    atomicAdd(((float4*)(g_B + (size_t)d * HCC)) + lane, r);
}

// ---------------- batch-norm stats + fold ----------------------------------
__global__ void k_bnstat() {
    int c = threadIdx.x;  // 128 threads
    double s = 0.0, q = 0.0;
    for (int r = blockIdx.x; r < NN; r += gridDim.x) {
        float v = g_B[(size_t)r * HCC + c];
        s += v;
        q += (double)v * v;
    }
    atomicAdd(&g_bnsum[c], s);
    atomicAdd(&g_bnsq[c], q);
}

__global__ void k_bnfinal(const float* __restrict__ gamma,
                          const float* __restrict__ beta) {
    int c = threadIdx.x;
    if (c >= HCC) return;
    float mu = (float)(g_bnsum[c] / (double)NN);
    float var = (float)(g_bnsq[c] / (double)NN) - mu * mu;
    float rstd = rsqrtf(var + BN_EPS);
    float sc = rstd * gamma[c];
    g_bnscale[c] = sc;
    g_bnshift[c] = beta[c] - mu * sc;
}

// ---------------- pooling (applies last BN+ReLU) + final FC ----------------
__global__ void k_pool() {
    int i = blockIdx.x * blockDim.x + threadIdx.x;
    if (i >= NN * 32) return;
    int n = i >> 5, q = i & 31;
    int g = g_batch[n];
    int c = q * 4;
    float4 v = ((const float4*)(g_B + (size_t)n * HCC))[q];
    v.x = fmaxf(v.x * g_bnscale[c + 0] + g_bnshift[c + 0], 0.f);
    v.y = fmaxf(v.y * g_bnscale[c + 1] + g_bnshift[c + 1], 0.f);
    v.z = fmaxf(v.z * g_bnscale[c + 2] + g_bnshift[c + 2], 0.f);
    v.w = fmaxf(v.w * g_bnscale[c + 3] + g_bnshift[c + 3], 0.f);
    atomicAdd(((float4*)(g_pool + (size_t)g * HCC)) + q, v);
}

__global__ void k_fc(const float* __restrict__ fcW,
                     const float* __restrict__ fcb,
                     float* __restrict__ out) {
    int g = threadIdx.x;
    if (g >= GG) return;
    float inv = 1.f / fmaxf(g_cnt[g], 1.f);
    float o0 = fcb[0], o1 = fcb[1];
    for (int c = 0; c < HCC; c++) {
        float p = g_pool[(size_t)g * HCC + c] * inv;
        o0 += p * fcW[c * 2 + 0];
        o1 += p * fcW[c * 2 + 1];
    }
    out[g * 2 + 0] = o0;
    out[g * 2 + 1] = o1;
}

// ---------------- launch ----------------------------------------------------
extern "C" void kernel_launch(void* const* d_in, const int* in_sizes, int n_in,
                              void* d_out, int out_size) {
    const float* x     = (const float*)d_in[0];
    const void*  ei    = d_in[1];
    const float* ea    = (const float*)d_in[2];
    const void*  batch = d_in[3];
    const float* efW   = (const float*)d_in[4];
    const float* efb   = (const float*)d_in[5];
    const float* Ws    = (const float*)d_in[6];
    const float* a_s   = (const float*)d_in[7];
    const float* a_d   = (const float*)d_in[8];
    const float* a_e   = (const float*)d_in[9];
    const float* lin_e = (const float*)d_in[10];
    const float* gamma = (const float*)d_in[12];
    const float* beta  = (const float*)d_in[13];
    const float* fcW   = (const float*)d_in[14];
    const float* fcb   = (const float*)d_in[15];
    float* out = (float*)d_out;

    k_detect<<<1, 32>>>((const int*)ei);
    k_init_pool<<<(GG * HCC + 255) / 256, 256>>>();
    k_prep<<<(EE + 255) / 256, 256>>>(ei, batch);
    k_m2<<<3 * EDIMC * 4 + 12, 32>>>(lin_e, a_e, efW, efb);
    k_e2<<<(EE + 255) / 256, 256>>>(ea);

    for (int l = 0; l < 3; l++) {
        k_gemm<<<(NN + 127) / 128, 256>>>(
            x, (l == 0) ? 1 : 0, (l == 0) ? 0 : 1,
            Ws + (size_t)l * HCC * HCC, a_s + l * HCC, a_d + l * HCC);
        k_init_layer<<<(NN * HCC + 255) / 256, 256>>>();
        k_alphaexp<<<(EE + 255) / 256, 256>>>(l);
        k_agg<<<(EE * 32 + 255) / 256, 256>>>();
        k_bnstat<<<512, 128>>>();
        k_bnfinal<<<1, 128>>>(gamma + l * HCC, beta + l * HCC);
    }

    k_pool<<<(NN * 32 + 255) / 256, 256>>>();
    k_fc<<<1, 256>>>(fcW, fcb, out);
}

// round 6
// speedup vs baseline: 2.7792x; 1.2653x over previous
#include <cuda_runtime.h>
#include <math.h>
#include <stdint.h>

#define NN 100000
#define EE 800000
#define GG 256
#define HCC 128
#define EDIMC 16
#define SLOPE 0.2f
#define BN_EPS 1e-5f

// ---------------- scratch (device globals; no allocations) ----------------
__device__ __align__(16) float g_A[(size_t)NN * HCC];    // post-GEMM features
__device__ __align__(16) float g_B[(size_t)NN * HCC];    // aggregated output (raw)
__device__ __align__(16) float g_alpha[(size_t)EE * 4];  // exp(alpha), CSR order
__device__ __align__(16) float g_e2[(size_t)3 * EE * 4]; // edge attn term, CSR order
__device__ __align__(16) float g_asrc[NN * 4];
__device__ __align__(16) float g_adst[NN * 4];
__device__ double g_bnS[512 * HCC];
__device__ double g_bnQ[512 * HCC];
__device__ float  g_bnscale[HCC];
__device__ float  g_bnshift[HCC];
__device__ float  g_M2[3 * EDIMC * 4];
__device__ float  g_c2[3 * 4];
__device__ __align__(16) float g_pool[GG * HCC];
__device__ float g_cnt[GG];
__device__ int   g_src[EE];     // original order
__device__ int   g_dst[EE];
__device__ int   g_srcs[EE];    // CSR order
__device__ int   g_dsts[EE];
__device__ int   g_pos[EE];     // original e -> CSR slot
__device__ int   g_rowptr[NN + 1];
__device__ int   g_deg[NN];
__device__ int   g_cur[NN];
__device__ int   g_batch[NN];
__device__ int   g_is64;

// ---------------- dtype detection (int64 vs int32 indices) ----------------
__global__ void k_detect(const int* __restrict__ ei_raw) {
    if (threadIdx.x == 0) {
        int ok = 1;
        for (int i = 0; i < 64; i++)
            if (ei_raw[2 * i + 1] != 0) ok = 0;
        g_is64 = ok;
    }
}

__global__ void k_init() {
    int i = blockIdx.x * blockDim.x + threadIdx.x;
    if (i < NN) { g_deg[i] = 0; g_cur[i] = 0; }
    if (i < GG * HCC) g_pool[i] = 0.f;
    if (i < GG) g_cnt[i] = 0.f;
}

__global__ void k_prep(const void* __restrict__ ei_raw,
                       const void* __restrict__ batch_raw) {
    int i = blockIdx.x * blockDim.x + threadIdx.x;
    int is64 = g_is64;
    if (i < EE) {
        int s, d;
        if (is64) {
            const long long* p = (const long long*)ei_raw;
            s = (int)p[i]; d = (int)p[EE + i];
        } else {
            const int* p = (const int*)ei_raw;
            s = p[i]; d = p[EE + i];
        }
        g_src[i] = s; g_dst[i] = d;
        atomicAdd(&g_deg[d], 1);
    }
    if (i < NN) {
        int b = is64 ? (int)((const long long*)batch_raw)[i]
                     : ((const int*)batch_raw)[i];
        g_batch[i] = b;
        atomicAdd(&g_cnt[b], 1.0f);
    }
}

// ---------------- exclusive scan over degrees (1 block, 1024 threads) -----
__global__ void k_scan() {
    __shared__ int swsum[32];
    int tid = threadIdx.x;
    int lane = tid & 31, wid = tid >> 5;
    int carry = 0;
    if (tid == 0) g_rowptr[0] = 0;
    for (int base = 0; base < NN; base += 1024) {
        int i = base + tid;
        int v = (i < NN) ? g_deg[i] : 0;
        int x = v;
#pragma unroll
        for (int off = 1; off < 32; off <<= 1) {
            int t = __shfl_up_sync(0xffffffffu, x, off);
            if (lane >= off) x += t;
        }
        if (lane == 31) swsum[wid] = x;
        __syncthreads();
        if (wid == 0) {
            int w = swsum[lane];
#pragma unroll
            for (int off = 1; off < 32; off <<= 1) {
                int t = __shfl_up_sync(0xffffffffu, w, off);
                if (lane >= off) w += t;
            }
            swsum[lane] = w;
        }
        __syncthreads();
        int add = (wid > 0) ? swsum[wid - 1] : 0;
        int incl = x + add + carry;
        if (i < NN) g_rowptr[i + 1] = incl;
        carry += swsum[31];
        __syncthreads();
    }
}

__global__ void k_scatter() {
    int e = blockIdx.x * blockDim.x + threadIdx.x;
    if (e >= EE) return;
    int s = g_src[e], d = g_dst[e];
    int p = atomicAdd(&g_cur[d], 1);
    int j = g_rowptr[d] + p;
    g_srcs[j] = s;
    g_dsts[j] = d;
    g_pos[e] = j;
}

// ---------------- M2 fold: warp per output --------------------------------
__global__ void k_m2(const float* __restrict__ lin_e,
                     const float* __restrict__ att_e,
                     const float* __restrict__ efW,
                     const float* __restrict__ efb) {
    int out = blockIdx.x;
    int lane = threadIdx.x;
    float t = 0.f;
    if (out < 3 * EDIMC * 4) {
        int l = out / (EDIMC * 4), r = out % (EDIMC * 4);
        int k16 = r / 4, h = r % 4;
        for (int idx = lane; idx < 32 * 32; idx += 32) {
            int k32 = idx >> 5, c = idx & 31;
            t += efW[k16 * 32 + k32] *
                 lin_e[(size_t)l * 32 * HCC + k32 * HCC + h * 32 + c] *
                 att_e[l * HCC + h * 32 + c];
        }
#pragma unroll
        for (int off = 16; off > 0; off >>= 1)
            t += __shfl_down_sync(0xffffffffu, t, off);
        if (lane == 0) g_M2[l * (EDIMC * 4) + k16 * 4 + h] = t;
    } else {
        int j = out - 3 * EDIMC * 4;
        if (j >= 12) return;
        int l = j / 4, h = j % 4;
        for (int idx = lane; idx < 32 * 32; idx += 32) {
            int k32 = idx >> 5, c = idx & 31;
            t += efb[k32] *
                 lin_e[(size_t)l * 32 * HCC + k32 * HCC + h * 32 + c] *
                 att_e[l * HCC + h * 32 + c];
        }
#pragma unroll
        for (int off = 16; off > 0; off >>= 1)
            t += __shfl_down_sync(0xffffffffu, t, off);
        if (lane == 0) g_c2[l * 4 + h] = t;
    }
}

// ---------------- edge term for all 3 layers, written in CSR order --------
__global__ void k_e2(const float* __restrict__ ea) {
    __shared__ float sM[3 * EDIMC * 4];
    __shared__ float sc[12];
    if (threadIdx.x < 3 * EDIMC * 4) sM[threadIdx.x] = g_M2[threadIdx.x];
    if (threadIdx.x < 12) sc[threadIdx.x] = g_c2[threadIdx.x];
    __syncthreads();
    int e = blockIdx.x * blockDim.x + threadIdx.x;
    if (e >= EE) return;
    float ev[EDIMC];
    const float4* ep = (const float4*)(ea + (size_t)e * EDIMC);
#pragma unroll
    for (int q = 0; q < 4; q++) {
        float4 v = ep[q];
        ev[q * 4 + 0] = v.x; ev[q * 4 + 1] = v.y;
        ev[q * 4 + 2] = v.z; ev[q * 4 + 3] = v.w;
    }
    int p = g_pos[e];
#pragma unroll
    for (int l = 0; l < 3; l++) {
        float o[4];
#pragma unroll
        for (int h = 0; h < 4; h++) {
            float t = sc[l * 4 + h];
#pragma unroll
            for (int k = 0; k < EDIMC; k++)
                t += ev[k] * sM[l * 64 + k * 4 + h];
            o[h] = t;
        }
        ((float4*)g_e2)[(size_t)l * EE + p] = make_float4(o[0], o[1], o[2], o[3]);
    }
}

// ---------------- fused GEMM (+BN-on-load, +attn-dot epilogue) -------------
__global__ __launch_bounds__(256, 2)
void k_gemm(const float* __restrict__ x_in, int use_x, int apply_bn,
            const float* __restrict__ W,
            const float* __restrict__ asl,
            const float* __restrict__ adl) {
    __shared__ float sA[16][132];
    __shared__ float sW[16][128];
    __shared__ float sAs[128], sAd[128];
    __shared__ float sScale[128], sShift[128];

    const float* A = use_x ? x_in : (const float*)g_B;

    int tid = threadIdx.x;
    int tx = tid & 15, ty = tid >> 4;
    int m0 = ty * 8, n0 = tx * 8;
    int row0 = blockIdx.x * 128;

    if (tid < 128) {
        sAs[tid] = asl[tid];
        sAd[tid] = adl[tid];
        if (apply_bn) {
            sScale[tid] = g_bnscale[tid];
            sShift[tid] = g_bnshift[tid];
        }
    }
    __syncthreads();

    float acc[8][8];
#pragma unroll
    for (int i = 0; i < 8; i++)
#pragma unroll
        for (int j = 0; j < 8; j++) acc[i][j] = 0.f;

    for (int kc = 0; kc < 8; kc++) {
        int k0 = kc * 16;
#pragma unroll
        for (int t = tid; t < 512; t += 256) {
            int k = t >> 5, c = t & 31;
            ((float4*)&sW[k][0])[c] =
                ((const float4*)(W + (size_t)(k0 + k) * HCC))[c];
        }
#pragma unroll
        for (int t = tid; t < 512; t += 256) {
            int r = t >> 2, q = t & 3;
            int gr = row0 + r;
            float4 v = (gr < NN)
                ? ((const float4*)(A + (size_t)gr * HCC))[kc * 4 + q]
                : make_float4(0.f, 0.f, 0.f, 0.f);
            if (apply_bn) {
                int c = k0 + q * 4;
                v.x = fmaxf(v.x * sScale[c + 0] + sShift[c + 0], 0.f);
                v.y = fmaxf(v.y * sScale[c + 1] + sShift[c + 1], 0.f);
                v.z = fmaxf(v.z * sScale[c + 2] + sShift[c + 2], 0.f);
                v.w = fmaxf(v.w * sScale[c + 3] + sShift[c + 3], 0.f);
            }
            sA[q * 4 + 0][r] = v.x;
            sA[q * 4 + 1][r] = v.y;
            sA[q * 4 + 2][r] = v.z;
            sA[q * 4 + 3][r] = v.w;
        }
        __syncthreads();
#pragma unroll
        for (int k = 0; k < 16; k++) {
            float4 a0 = *(float4*)&sA[k][m0];
            float4 a1 = *(float4*)&sA[k][m0 + 4];
            float4 b0 = *(float4*)&sW[k][n0];
            float4 b1 = *(float4*)&sW[k][n0 + 4];
            float aa[8] = {a0.x, a0.y, a0.z, a0.w, a1.x, a1.y, a1.z, a1.w};
            float bb[8] = {b0.x, b0.y, b0.z, b0.w, b1.x, b1.y, b1.z, b1.w};
#pragma unroll
            for (int i = 0; i < 8; i++)
#pragma unroll
                for (int j = 0; j < 8; j++)
                    acc[i][j] += aa[i] * bb[j];
        }
        __syncthreads();
    }

    int h = tx >> 2;
#pragma unroll
    for (int i = 0; i < 8; i++) {
        int r = row0 + m0 + i;
        float ps = 0.f, pd = 0.f;
#pragma unroll
        for (int j = 0; j < 8; j++) {
            ps += acc[i][j] * sAs[n0 + j];
            pd += acc[i][j] * sAd[n0 + j];
        }
#pragma unroll
        for (int off = 1; off < 4; off <<= 1) {
            ps += __shfl_xor_sync(0xffffffffu, ps, off, 4);
            pd += __shfl_xor_sync(0xffffffffu, pd, off, 4);
        }
        if (r < NN) {
            float4 o0 = {acc[i][0], acc[i][1], acc[i][2], acc[i][3]};
            float4 o1 = {acc[i][4], acc[i][5], acc[i][6], acc[i][7]};
            float4* Cr = (float4*)(g_A + (size_t)r * HCC);
            Cr[tx * 2] = o0;
            Cr[tx * 2 + 1] = o1;
            if ((tx & 3) == 0) {
                g_asrc[r * 4 + h] = ps;
                g_adst[r * 4 + h] = pd;
            }
        }
    }
}

// ---------------- edge weights: w = exp(leaky(asrc+adst+e2)), CSR order ----
__global__ void k_edge(int l) {
    int j = blockIdx.x * blockDim.x + threadIdx.x;
    if (j >= EE) return;
    int s = g_srcs[j], d = g_dsts[j];
    float4 as = ((const float4*)g_asrc)[s];
    float4 ad = ((const float4*)g_adst)[d];
    float4 e2 = ((const float4*)g_e2)[(size_t)l * EE + j];
    float a0 = as.x + ad.x + e2.x;
    float a1 = as.y + ad.y + e2.y;
    float a2 = as.z + ad.z + e2.z;
    float a3 = as.w + ad.w + e2.w;
    a0 = (a0 > 0.f) ? a0 : SLOPE * a0;
    a1 = (a1 > 0.f) ? a1 : SLOPE * a1;
    a2 = (a2 > 0.f) ? a2 : SLOPE * a2;
    a3 = (a3 > 0.f) ? a3 : SLOPE * a3;
    ((float4*)g_alpha)[j] =
        make_float4(__expf(a0), __expf(a1), __expf(a2), __expf(a3));
}

// ---------------- atomic-free aggregate: warp per destination node --------
__global__ __launch_bounds__(256)
void k_agg() {
    int node = (blockIdx.x * blockDim.x + threadIdx.x) >> 5;
    int lane = threadIdx.x & 31;
    if (node >= NN) return;
    int start = g_rowptr[node], end = g_rowptr[node + 1];

    // pass 1: denominator
    float4 ds = make_float4(0.f, 0.f, 0.f, 0.f);
    for (int j = start + lane; j < end; j += 32) {
        float4 w = ((const float4*)g_alpha)[j];
        ds.x += w.x; ds.y += w.y; ds.z += w.z; ds.w += w.w;
    }
#pragma unroll
    for (int off = 16; off > 0; off >>= 1) {
        ds.x += __shfl_xor_sync(0xffffffffu, ds.x, off);
        ds.y += __shfl_xor_sync(0xffffffffu, ds.y, off);
        ds.z += __shfl_xor_sync(0xffffffffu, ds.z, off);
        ds.w += __shfl_xor_sync(0xffffffffu, ds.w, off);
    }
    int h = lane >> 3;
    float dh = (h == 0) ? ds.x : (h == 1) ? ds.y : (h == 2) ? ds.z : ds.w;
    float inv = 1.f / (dh + 1e-16f);

    // pass 2: weighted gather-accumulate
    float4 acc = make_float4(0.f, 0.f, 0.f, 0.f);
    for (int j = start; j < end; j++) {
        int s = g_srcs[j];
        float coef = g_alpha[(size_t)j * 4 + h] * inv;
        float4 v = ((const float4*)(g_A + (size_t)s * HCC))[lane];
        acc.x += coef * v.x; acc.y += coef * v.y;
        acc.z += coef * v.z; acc.w += coef * v.w;
    }
    ((float4*)(g_B + (size_t)node * HCC))[lane] = acc;
}

// ---------------- batch-norm stats (atomic-free partials) ------------------
__global__ void k_bnstat() {
    int c = threadIdx.x;  // 128 threads, grid must be 512
    double s = 0.0, q = 0.0;
    for (int r = blockIdx.x; r < NN; r += 512) {
        float v = g_B[(size_t)r * HCC + c];
        s += v;
        q += (double)v * v;
    }
    g_bnS[blockIdx.x * HCC + c] = s;
    g_bnQ[blockIdx.x * HCC + c] = q;
}

__global__ void k_bnfinal(const float* __restrict__ gamma,
                          const float* __restrict__ beta) {
    __shared__ double ss[256], sq[256];
    int c = blockIdx.x;   // 128 blocks, one per channel
    int t = threadIdx.x;  // 256 threads
    double s = g_bnS[t * HCC + c] + g_bnS[(t + 256) * HCC + c];
    double q = g_bnQ[t * HCC + c] + g_bnQ[(t + 256) * HCC + c];
    ss[t] = s; sq[t] = q;
    __syncthreads();
#pragma unroll
    for (int off = 128; off > 0; off >>= 1) {
        if (t < off) { ss[t] += ss[t + off]; sq[t] += sq[t + off]; }
        __syncthreads();
    }
    if (t == 0) {
        float mu = (float)(ss[0] / (double)NN);
        float var = (float)(sq[0] / (double)NN) - mu * mu;
        float rstd = rsqrtf(var + BN_EPS);
        float sc = rstd * gamma[c];
        g_bnscale[c] = sc;
        g_bnshift[c] = beta[c] - mu * sc;
    }
}

// ---------------- pooling (applies last BN+ReLU) + final FC ----------------
__global__ void k_pool() {
    int i = blockIdx.x * blockDim.x + threadIdx.x;
    if (i >= NN * 32) return;
    int n = i >> 5, q = i & 31;
    int g = g_batch[n];
    int c = q * 4;
    float4 v = ((const float4*)(g_B + (size_t)n * HCC))[q];
    v.x = fmaxf(v.x * g_bnscale[c + 0] + g_bnshift[c + 0], 0.f);
    v.y = fmaxf(v.y * g_bnscale[c + 1] + g_bnshift[c + 1], 0.f);
    v.z = fmaxf(v.z * g_bnscale[c + 2] + g_bnshift[c + 2], 0.f);
    v.w = fmaxf(v.w * g_bnscale[c + 3] + g_bnshift[c + 3], 0.f);
    atomicAdd(((float4*)(g_pool + (size_t)g * HCC)) + q, v);
}

__global__ void k_fc(const float* __restrict__ fcW,
                     const float* __restrict__ fcb,
                     float* __restrict__ out) {
    int g = threadIdx.x;
    if (g >= GG) return;
    float inv = 1.f / fmaxf(g_cnt[g], 1.f);
    float o0 = fcb[0], o1 = fcb[1];
    for (int c = 0; c < HCC; c++) {
        float p = g_pool[(size_t)g * HCC + c] * inv;
        o0 += p * fcW[c * 2 + 0];
        o1 += p * fcW[c * 2 + 1];
    }
    out[g * 2 + 0] = o0;
    out[g * 2 + 1] = o1;
}

// ---------------- launch ----------------------------------------------------
extern "C" void kernel_launch(void* const* d_in, const int* in_sizes, int n_in,
                              void* d_out, int out_size) {
    const float* x     = (const float*)d_in[0];
    const void*  ei    = d_in[1];
    const float* ea    = (const float*)d_in[2];
    const void*  batch = d_in[3];
    const float* efW   = (const float*)d_in[4];
    const float* efb   = (const float*)d_in[5];
    const float* Ws    = (const float*)d_in[6];
    const float* a_s   = (const float*)d_in[7];
    const float* a_d   = (const float*)d_in[8];
    const float* a_e   = (const float*)d_in[9];
    const float* lin_e = (const float*)d_in[10];
    const float* gamma = (const float*)d_in[12];
    const float* beta  = (const float*)d_in[13];
    const float* fcW   = (const float*)d_in[14];
    const float* fcb   = (const float*)d_in[15];
    float* out = (float*)d_out;

    k_detect<<<1, 32>>>((const int*)ei);
    k_init<<<(NN + 255) / 256, 256>>>();
    k_prep<<<(EE + 255) / 256, 256>>>(ei, batch);
    k_scan<<<1, 1024>>>();
    k_scatter<<<(EE + 255) / 256, 256>>>();
    k_m2<<<3 * EDIMC * 4 + 12, 32>>>(lin_e, a_e, efW, efb);
    k_e2<<<(EE + 255) / 256, 256>>>(ea);

    for (int l = 0; l < 3; l++) {
        k_gemm<<<(NN + 127) / 128, 256>>>(
            x, (l == 0) ? 1 : 0, (l == 0) ? 0 : 1,
            Ws + (size_t)l * HCC * HCC, a_s + l * HCC, a_d + l * HCC);
        k_edge<<<(EE + 255) / 256, 256>>>(l);
        k_agg<<<(NN * 32 + 255) / 256, 256>>>();
        k_bnstat<<<512, 128>>>();
        k_bnfinal<<<128, 256>>>(gamma + l * HCC, beta + l * HCC);
    }

    k_pool<<<(NN * 32 + 255) / 256, 256>>>();
    k_fc<<<1, 256>>>(fcW, fcb, out);
}

// round 7
// speedup vs baseline: 2.9809x; 1.0726x over previous
#include <cuda_runtime.h>
#include <math.h>
#include <stdint.h>

#define NN 100000
#define EE 800000
#define GG 256
#define HCC 128
#define EDIMC 16
#define SLOPE 0.2f
#define BN_EPS 1e-5f
#define NSCAN ((NN + 1023) / 1024)   // 98 blocks

// ---------------- scratch (device globals; no allocations) ----------------
__device__ __align__(16) float g_A[(size_t)NN * HCC];    // post-GEMM features
__device__ __align__(16) float g_B[(size_t)NN * HCC];    // aggregated output (raw)
__device__ __align__(16) float g_alpha[(size_t)EE * 4];  // exp(alpha), CSR order
__device__ __align__(16) float g_e2[(size_t)3 * EE * 4]; // edge attn term, CSR order
__device__ __align__(16) float g_asrc[NN * 4];
__device__ __align__(16) float g_adst[NN * 4];
__device__ double g_bnS[512 * HCC];
__device__ double g_bnQ[512 * HCC];
__device__ float  g_bnscale[HCC];
__device__ float  g_bnshift[HCC];
__device__ float  g_M2[3 * EDIMC * 4];
__device__ float  g_c2[3 * 4];
__device__ __align__(16) float g_pool[GG * HCC];
__device__ float g_cnt[GG];
__device__ int   g_src[EE];     // original order
__device__ int   g_dst[EE];
__device__ int   g_srcs[EE];    // CSR order
__device__ int   g_pos[EE];     // original e -> CSR slot
__device__ int   g_rowptr[NN + 1];
__device__ int   g_deg[NN];
__device__ int   g_cur[NN];
__device__ int   g_batch[NN];
__device__ int   g_bsum[128];
__device__ int   g_boff[128];
__device__ int   g_is64;

// ---------------- dtype detection (int64 vs int32 indices) ----------------
__global__ void k_detect(const int* __restrict__ ei_raw) {
    if (threadIdx.x == 0) {
        int ok = 1;
        for (int i = 0; i < 64; i++)
            if (ei_raw[2 * i + 1] != 0) ok = 0;
        g_is64 = ok;
    }
}

__global__ void k_init() {
    int i = blockIdx.x * blockDim.x + threadIdx.x;
    if (i < NN) { g_deg[i] = 0; g_cur[i] = 0; }
    if (i < GG * HCC) g_pool[i] = 0.f;
    if (i < GG) g_cnt[i] = 0.f;
}

__global__ void k_prep(const void* __restrict__ ei_raw,
                       const void* __restrict__ batch_raw) {
    int i = blockIdx.x * blockDim.x + threadIdx.x;
    int is64 = g_is64;
    if (i < EE) {
        int s, d;
        if (is64) {
            const long long* p = (const long long*)ei_raw;
            s = (int)p[i]; d = (int)p[EE + i];
        } else {
            const int* p = (const int*)ei_raw;
            s = p[i]; d = p[EE + i];
        }
        g_src[i] = s; g_dst[i] = d;
        atomicAdd(&g_deg[d], 1);
    }
    if (i < NN) {
        int b = is64 ? (int)((const long long*)batch_raw)[i]
                     : ((const int*)batch_raw)[i];
        g_batch[i] = b;
        atomicAdd(&g_cnt[b], 1.0f);
    }
}

// ---------------- parallel 3-phase exclusive scan -------------------------
__global__ void k_scan1() {   // grid NSCAN, block 1024: per-block inclusive
    __shared__ int swsum[32];
    int tid = threadIdx.x;
    int lane = tid & 31, wid = tid >> 5;
    int i = blockIdx.x * 1024 + tid;
    int x = (i < NN) ? g_deg[i] : 0;
#pragma unroll
    for (int off = 1; off < 32; off <<= 1) {
        int t = __shfl_up_sync(0xffffffffu, x, off);
        if (lane >= off) x += t;
    }
    if (lane == 31) swsum[wid] = x;
    __syncthreads();
    if (wid == 0) {
        int w = swsum[lane];
#pragma unroll
        for (int off = 1; off < 32; off <<= 1) {
            int t = __shfl_up_sync(0xffffffffu, w, off);
            if (lane >= off) w += t;
        }
        swsum[lane] = w;
    }
    __syncthreads();
    int incl = x + ((wid > 0) ? swsum[wid - 1] : 0);
    if (i < NN) g_rowptr[i + 1] = incl;
    if (tid == 1023) g_bsum[blockIdx.x] = incl;
    if (i == 0) g_rowptr[0] = 0;
}

__global__ void k_scan2() {   // 1 block, 128 threads: scan block totals
    __shared__ int s[128];
    int t = threadIdx.x;
    int v = (t < NSCAN) ? g_bsum[t] : 0;
    s[t] = v;
    __syncthreads();
#pragma unroll
    for (int off = 1; off < 128; off <<= 1) {
        int u = (t >= off) ? s[t - off] : 0;
        __syncthreads();
        s[t] += u;
        __syncthreads();
    }
    if (t < NSCAN) g_boff[t] = s[t] - v;   // exclusive
}

__global__ void k_scan3() {   // add block offsets
    int i = blockIdx.x * blockDim.x + threadIdx.x;
    if (i < NN) g_rowptr[i + 1] += g_boff[i >> 10];
}

__global__ void k_scatter() {
    int e = blockIdx.x * blockDim.x + threadIdx.x;
    if (e >= EE) return;
    int s = g_src[e], d = g_dst[e];
    int p = atomicAdd(&g_cur[d], 1);
    int j = g_rowptr[d] + p;
    g_srcs[j] = s;
    g_pos[e] = j;
}

// ---------------- M2 fold: warp per output --------------------------------
__global__ void k_m2(const float* __restrict__ lin_e,
                     const float* __restrict__ att_e,
                     const float* __restrict__ efW,
                     const float* __restrict__ efb) {
    int out = blockIdx.x;
    int lane = threadIdx.x;
    float t = 0.f;
    if (out < 3 * EDIMC * 4) {
        int l = out / (EDIMC * 4), r = out % (EDIMC * 4);
        int k16 = r / 4, h = r % 4;
        for (int idx = lane; idx < 32 * 32; idx += 32) {
            int k32 = idx >> 5, c = idx & 31;
            t += efW[k16 * 32 + k32] *
                 lin_e[(size_t)l * 32 * HCC + k32 * HCC + h * 32 + c] *
                 att_e[l * HCC + h * 32 + c];
        }
#pragma unroll
        for (int off = 16; off > 0; off >>= 1)
            t += __shfl_down_sync(0xffffffffu, t, off);
        if (lane == 0) g_M2[l * (EDIMC * 4) + k16 * 4 + h] = t;
    } else {
        int j = out - 3 * EDIMC * 4;
        if (j >= 12) return;
        int l = j / 4, h = j % 4;
        for (int idx = lane; idx < 32 * 32; idx += 32) {
            int k32 = idx >> 5, c = idx & 31;
            t += efb[k32] *
                 lin_e[(size_t)l * 32 * HCC + k32 * HCC + h * 32 + c] *
                 att_e[l * HCC + h * 32 + c];
        }
#pragma unroll
        for (int off = 16; off > 0; off >>= 1)
            t += __shfl_down_sync(0xffffffffu, t, off);
        if (lane == 0) g_c2[l * 4 + h] = t;
    }
}

// ---------------- edge term for all 3 layers, written in CSR order --------
__global__ void k_e2(const float* __restrict__ ea) {
    __shared__ float sM[3 * EDIMC * 4];
    __shared__ float sc[12];
    if (threadIdx.x < 3 * EDIMC * 4) sM[threadIdx.x] = g_M2[threadIdx.x];
    if (threadIdx.x < 12) sc[threadIdx.x] = g_c2[threadIdx.x];
    __syncthreads();
    int e = blockIdx.x * blockDim.x + threadIdx.x;
    if (e >= EE) return;
    float ev[EDIMC];
    const float4* ep = (const float4*)(ea + (size_t)e * EDIMC);
#pragma unroll
    for (int q = 0; q < 4; q++) {
        float4 v = ep[q];
        ev[q * 4 + 0] = v.x; ev[q * 4 + 1] = v.y;
        ev[q * 4 + 2] = v.z; ev[q * 4 + 3] = v.w;
    }
    int p = g_pos[e];
#pragma unroll
    for (int l = 0; l < 3; l++) {
        float o[4];
#pragma unroll
        for (int h = 0; h < 4; h++) {
            float t = sc[l * 4 + h];
#pragma unroll
            for (int k = 0; k < EDIMC; k++)
                t += ev[k] * sM[l * 64 + k * 4 + h];
            o[h] = t;
        }
        ((float4*)g_e2)[(size_t)l * EE + p] = make_float4(o[0], o[1], o[2], o[3]);
    }
}

// ---------------- fused GEMM (+BN-on-load, +attn-dot epilogue) -------------
__global__ __launch_bounds__(256, 2)
void k_gemm(const float* __restrict__ x_in, int use_x, int apply_bn,
            const float* __restrict__ W,
            const float* __restrict__ asl,
            const float* __restrict__ adl) {
    __shared__ float sA[16][132];
    __shared__ float sW[16][128];
    __shared__ float sAs[128], sAd[128];
    __shared__ float sScale[128], sShift[128];

    const float* A = use_x ? x_in : (const float*)g_B;

    int tid = threadIdx.x;
    int tx = tid & 15, ty = tid >> 4;
    int m0 = ty * 8, n0 = tx * 8;
    int row0 = blockIdx.x * 128;

    if (tid < 128) {
        sAs[tid] = asl[tid];
        sAd[tid] = adl[tid];
        if (apply_bn) {
            sScale[tid] = g_bnscale[tid];
            sShift[tid] = g_bnshift[tid];
        }
    }
    __syncthreads();

    float acc[8][8];
#pragma unroll
    for (int i = 0; i < 8; i++)
#pragma unroll
        for (int j = 0; j < 8; j++) acc[i][j] = 0.f;

    for (int kc = 0; kc < 8; kc++) {
        int k0 = kc * 16;
#pragma unroll
        for (int t = tid; t < 512; t += 256) {
            int k = t >> 5, c = t & 31;
            ((float4*)&sW[k][0])[c] =
                ((const float4*)(W + (size_t)(k0 + k) * HCC))[c];
        }
#pragma unroll
        for (int t = tid; t < 512; t += 256) {
            int r = t >> 2, q = t & 3;
            int gr = row0 + r;
            float4 v = (gr < NN)
                ? ((const float4*)(A + (size_t)gr * HCC))[kc * 4 + q]
                : make_float4(0.f, 0.f, 0.f, 0.f);
            if (apply_bn) {
                int c = k0 + q * 4;
                v.x = fmaxf(v.x * sScale[c + 0] + sShift[c + 0], 0.f);
                v.y = fmaxf(v.y * sScale[c + 1] + sShift[c + 1], 0.f);
                v.z = fmaxf(v.z * sScale[c + 2] + sShift[c + 2], 0.f);
                v.w = fmaxf(v.w * sScale[c + 3] + sShift[c + 3], 0.f);
            }
            sA[q * 4 + 0][r] = v.x;
            sA[q * 4 + 1][r] = v.y;
            sA[q * 4 + 2][r] = v.z;
            sA[q * 4 + 3][r] = v.w;
        }
        __syncthreads();
#pragma unroll
        for (int k = 0; k < 16; k++) {
            float4 a0 = *(float4*)&sA[k][m0];
            float4 a1 = *(float4*)&sA[k][m0 + 4];
            float4 b0 = *(float4*)&sW[k][n0];
            float4 b1 = *(float4*)&sW[k][n0 + 4];
            float aa[8] = {a0.x, a0.y, a0.z, a0.w, a1.x, a1.y, a1.z, a1.w};
            float bb[8] = {b0.x, b0.y, b0.z, b0.w, b1.x, b1.y, b1.z, b1.w};
#pragma unroll
            for (int i = 0; i < 8; i++)
#pragma unroll
                for (int j = 0; j < 8; j++)
                    acc[i][j] += aa[i] * bb[j];
        }
        __syncthreads();
    }

    int h = tx >> 2;
#pragma unroll
    for (int i = 0; i < 8; i++) {
        int r = row0 + m0 + i;
        float ps = 0.f, pd = 0.f;
#pragma unroll
        for (int j = 0; j < 8; j++) {
            ps += acc[i][j] * sAs[n0 + j];
            pd += acc[i][j] * sAd[n0 + j];
        }
#pragma unroll
        for (int off = 1; off < 4; off <<= 1) {
            ps += __shfl_xor_sync(0xffffffffu, ps, off, 4);
            pd += __shfl_xor_sync(0xffffffffu, pd, off, 4);
        }
        if (r < NN) {
            float4 o0 = {acc[i][0], acc[i][1], acc[i][2], acc[i][3]};
            float4 o1 = {acc[i][4], acc[i][5], acc[i][6], acc[i][7]};
            float4* Cr = (float4*)(g_A + (size_t)r * HCC);
            Cr[tx * 2] = o0;
            Cr[tx * 2 + 1] = o1;
            if ((tx & 3) == 0) {
                g_asrc[r * 4 + h] = ps;
                g_adst[r * 4 + h] = pd;
            }
        }
    }
}

// -------- fused edge-weight + atomic-free aggregate: warp per node --------
__global__ __launch_bounds__(256)
void k_agg(int l) {
    int node = (blockIdx.x * blockDim.x + threadIdx.x) >> 5;
    int lane = threadIdx.x & 31;
    if (node >= NN) return;
    int start = g_rowptr[node], end = g_rowptr[node + 1];

    // pass 1: compute w = exp(leaky(asrc+adst+e2)), store, accumulate denom
    float4 ad = ((const float4*)g_adst)[node];   // broadcast load
    float4 ds = make_float4(0.f, 0.f, 0.f, 0.f);
    for (int j = start + lane; j < end; j += 32) {
        int s = g_srcs[j];
        float4 as = ((const float4*)g_asrc)[s];
        float4 e2 = ((const float4*)g_e2)[(size_t)l * EE + j];
        float a0 = as.x + ad.x + e2.x;
        float a1 = as.y + ad.y + e2.y;
        float a2 = as.z + ad.z + e2.z;
        float a3 = as.w + ad.w + e2.w;
        a0 = (a0 > 0.f) ? a0 : SLOPE * a0;
        a1 = (a1 > 0.f) ? a1 : SLOPE * a1;
        a2 = (a2 > 0.f) ? a2 : SLOPE * a2;
        a3 = (a3 > 0.f) ? a3 : SLOPE * a3;
        float4 w = make_float4(__expf(a0), __expf(a1), __expf(a2), __expf(a3));
        ((float4*)g_alpha)[j] = w;
        ds.x += w.x; ds.y += w.y; ds.z += w.z; ds.w += w.w;
    }
    __syncwarp();
#pragma unroll
    for (int off = 16; off > 0; off >>= 1) {
        ds.x += __shfl_xor_sync(0xffffffffu, ds.x, off);
        ds.y += __shfl_xor_sync(0xffffffffu, ds.y, off);
        ds.z += __shfl_xor_sync(0xffffffffu, ds.z, off);
        ds.w += __shfl_xor_sync(0xffffffffu, ds.w, off);
    }
    int h = lane >> 3;
    float dh = (h == 0) ? ds.x : (h == 1) ? ds.y : (h == 2) ? ds.z : ds.w;
    float inv = 1.f / (dh + 1e-16f);

    // pass 2: weighted gather-accumulate
    float4 acc = make_float4(0.f, 0.f, 0.f, 0.f);
    for (int j = start; j < end; j++) {
        int s = g_srcs[j];
        float coef = g_alpha[(size_t)j * 4 + h] * inv;
        float4 v = ((const float4*)(g_A + (size_t)s * HCC))[lane];
        acc.x += coef * v.x; acc.y += coef * v.y;
        acc.z += coef * v.z; acc.w += coef * v.w;
    }
    ((float4*)(g_B + (size_t)node * HCC))[lane] = acc;
}

// ---------------- batch-norm stats (atomic-free partials) ------------------
__global__ void k_bnstat() {
    int c = threadIdx.x;  // 128 threads, grid must be 512
    double s = 0.0, q = 0.0;
    for (int r = blockIdx.x; r < NN; r += 512) {
        float v = g_B[(size_t)r * HCC + c];
        s += v;
        q += (double)v * v;
    }
    g_bnS[blockIdx.x * HCC + c] = s;
    g_bnQ[blockIdx.x * HCC + c] = q;
}

__global__ void k_bnfinal(const float* __restrict__ gamma,
                          const float* __restrict__ beta) {
    __shared__ double ss[256], sq[256];
    int c = blockIdx.x;   // 128 blocks, one per channel
    int t = threadIdx.x;  // 256 threads
    double s = g_bnS[t * HCC + c] + g_bnS[(t + 256) * HCC + c];
    double q = g_bnQ[t * HCC + c] + g_bnQ[(t + 256) * HCC + c];
    ss[t] = s; sq[t] = q;
    __syncthreads();
#pragma unroll
    for (int off = 128; off > 0; off >>= 1) {
        if (t < off) { ss[t] += ss[t + off]; sq[t] += sq[t + off]; }
        __syncthreads();
    }
    if (t == 0) {
        float mu = (float)(ss[0] / (double)NN);
        float var = (float)(sq[0] / (double)NN) - mu * mu;
        float rstd = rsqrtf(var + BN_EPS);
        float sc = rstd * gamma[c];
        g_bnscale[c] = sc;
        g_bnshift[c] = beta[c] - mu * sc;
    }
}

// ---------------- pooling (applies last BN+ReLU) + final FC ----------------
__global__ void k_pool() {
    int i = blockIdx.x * blockDim.x + threadIdx.x;
    if (i >= NN * 32) return;
    int n = i >> 5, q = i & 31;
    int g = g_batch[n];
    int c = q * 4;
    float4 v = ((const float4*)(g_B + (size_t)n * HCC))[q];
    v.x = fmaxf(v.x * g_bnscale[c + 0] + g_bnshift[c + 0], 0.f);
    v.y = fmaxf(v.y * g_bnscale[c + 1] + g_bnshift[c + 1], 0.f);
    v.z = fmaxf(v.z * g_bnscale[c + 2] + g_bnshift[c + 2], 0.f);
    v.w = fmaxf(v.w * g_bnscale[c + 3] + g_bnshift[c + 3], 0.f);
    atomicAdd(((float4*)(g_pool + (size_t)g * HCC)) + q, v);
}

__global__ void k_fc(const float* __restrict__ fcW,
                     const float* __restrict__ fcb,
                     float* __restrict__ out) {
    int g = threadIdx.x;
    if (g >= GG) return;
    float inv = 1.f / fmaxf(g_cnt[g], 1.f);
    float o0 = fcb[0], o1 = fcb[1];
    for (int c = 0; c < HCC; c++) {
        float p = g_pool[(size_t)g * HCC + c] * inv;
        o0 += p * fcW[c * 2 + 0];
        o1 += p * fcW[c * 2 + 1];
    }
    out[g * 2 + 0] = o0;
    out[g * 2 + 1] = o1;
}

// ---------------- launch ----------------------------------------------------
extern "C" void kernel_launch(void* const* d_in, const int* in_sizes, int n_in,
                              void* d_out, int out_size) {
    const float* x     = (const float*)d_in[0];
    const void*  ei    = d_in[1];
    const float* ea    = (const float*)d_in[2];
    const void*  batch = d_in[3];
    const float* efW   = (const float*)d_in[4];
    const float* efb   = (const float*)d_in[5];
    const float* Ws    = (const float*)d_in[6];
    const float* a_s   = (const float*)d_in[7];
    const float* a_d   = (const float*)d_in[8];
    const float* a_e   = (const float*)d_in[9];
    const float* lin_e = (const float*)d_in[10];
    const float* gamma = (const float*)d_in[12];
    const float* beta  = (const float*)d_in[13];
    const float* fcW   = (const float*)d_in[14];
    const float* fcb   = (const float*)d_in[15];
    float* out = (float*)d_out;

    k_detect<<<1, 32>>>((const int*)ei);
    k_init<<<(NN + 255) / 256, 256>>>();
    k_prep<<<(EE + 255) / 256, 256>>>(ei, batch);
    k_scan1<<<NSCAN, 1024>>>();
    k_scan2<<<1, 128>>>();
    k_scan3<<<(NN + 1023) / 1024, 1024>>>();
    k_scatter<<<(EE + 255) / 256, 256>>>();
    k_m2<<<3 * EDIMC * 4 + 12, 32>>>(lin_e, a_e, efW, efb);
    k_e2<<<(EE + 255) / 256, 256>>>(ea);

    for (int l = 0; l < 3; l++) {
        k_gemm<<<(NN + 127) / 128, 256>>>(
            x, (l == 0) ? 1 : 0, (l == 0) ? 0 : 1,
            Ws + (size_t)l * HCC * HCC, a_s + l * HCC, a_d + l * HCC);
        k_agg<<<(NN * 32 + 255) / 256, 256>>>(l);
        k_bnstat<<<512, 128>>>();
        k_bnfinal<<<128, 256>>>(gamma + l * HCC, beta + l * HCC);
    }

    k_pool<<<(NN * 32 + 255) / 256, 256>>>();
    k_fc<<<1, 256>>>(fcW, fcb, out);
}

// round 13
// speedup vs baseline: 3.1161x; 1.0454x over previous
#include <cuda_runtime.h>
#include <cuda_bf16.h>
#include <math.h>
#include <stdint.h>

#define NN 100000
#define EE 800000
#define GG 256
#define HCC 128
#define EDIMC 16
#define SLOPE 0.2f
#define BN_EPS 1e-5f
#define NSCAN ((NN + 1023) / 1024)   // 98 blocks

// padded bf16 row stride for MMA smem tiles (conflict-free fragment LDS)
#define TSTRIDE 136                   // elems; 272 bytes per row
#define TBYTES  (128 * TSTRIDE * 2)   // 34816 bytes per tile
// dynamic smem layout (bytes)
#define SAS_OFF 0
#define SAD_OFF 512
#define SSC_OFF 1024
#define SSH_OFF 1536
#define AH_OFF  2048
#define AL_OFF  (AH_OFF + TBYTES)
#define BH_OFF  (AL_OFF + TBYTES)
#define BL_OFF  (BH_OFF + TBYTES)
#define SMEM_MM (BL_OFF + TBYTES)     // 141312 bytes

// ---------------- scratch (device globals; no allocations) ----------------
__device__ __align__(16) float g_A[(size_t)NN * HCC];    // post-GEMM features
__device__ __align__(16) float g_B[(size_t)NN * HCC];    // aggregated output (raw)
__device__ __align__(16) float g_alpha[(size_t)EE * 4];  // exp(alpha), CSR order
__device__ __align__(16) float g_e2[(size_t)3 * EE * 4]; // edge attn term, CSR order
__device__ __align__(16) float g_asrc[NN * 4];
__device__ __align__(16) float g_adst[NN * 4];
__device__ double g_bnS[512 * HCC];
__device__ double g_bnQ[512 * HCC];
__device__ float  g_bnscale[HCC];
__device__ float  g_bnshift[HCC];
__device__ float  g_M2[3 * EDIMC * 4];
__device__ float  g_c2[3 * 4];
__device__ __align__(16) float g_pool[GG * HCC];
__device__ float g_cnt[GG];
// W^T split: [layer][hi/lo][128 rows(n) * TSTRIDE cols(k)] bf16, padded
__device__ __align__(16) __nv_bfloat16 g_Wtp[3][2][128 * TSTRIDE];
__device__ int   g_src[EE];
__device__ int   g_dst[EE];
__device__ int   g_srcs[EE];
__device__ int   g_pos[EE];
__device__ int   g_rowptr[NN + 1];
__device__ int   g_deg[NN];
__device__ int   g_cur[NN];
__device__ int   g_batch[NN];
__device__ int   g_bsum[128];
__device__ int   g_boff[128];
__device__ int   g_is64;

// ---------------- dtype detection (int64 vs int32 indices) ----------------
__global__ void k_detect(const int* __restrict__ ei_raw) {
    if (threadIdx.x == 0) {
        int ok = 1;
        for (int i = 0; i < 64; i++)
            if (ei_raw[2 * i + 1] != 0) ok = 0;
        g_is64 = ok;
    }
}

__global__ void k_init() {
    int i = blockIdx.x * blockDim.x + threadIdx.x;
    if (i < NN) { g_deg[i] = 0; g_cur[i] = 0; }
    if (i < GG * HCC) g_pool[i] = 0.f;
    if (i < GG) g_cnt[i] = 0.f;
}

__global__ void k_prep(const void* __restrict__ ei_raw,
                       const void* __restrict__ batch_raw) {
    int i = blockIdx.x * blockDim.x + threadIdx.x;
    int is64 = g_is64;
    if (i < EE) {
        int s, d;
        if (is64) {
            const long long* p = (const long long*)ei_raw;
            s = (int)p[i]; d = (int)p[EE + i];
        } else {
            const int* p = (const int*)ei_raw;
            s = p[i]; d = p[EE + i];
        }
        g_src[i] = s; g_dst[i] = d;
        atomicAdd(&g_deg[d], 1);
    }
    if (i < NN) {
        int b = is64 ? (int)((const long long*)batch_raw)[i]
                     : ((const int*)batch_raw)[i];
        g_batch[i] = b;
        atomicAdd(&g_cnt[b], 1.0f);
    }
}

// ---------------- W transpose + bf16 hi/lo split, padded row-major --------
__global__ void k_wprep(const float* __restrict__ Ws) {
    int id = blockIdx.x * blockDim.x + threadIdx.x;
    if (id >= 3 * 16384) return;
    int l = id / 16384, rem = id % 16384;
    int n = rem / 128, k = rem % 128;
    float w = Ws[(size_t)l * 16384 + k * 128 + n];   // B[n][k] = W[k][n]
    __nv_bfloat16 hi = __float2bfloat16(w);
    float lof = w - __bfloat162float(hi);
    g_Wtp[l][0][n * TSTRIDE + k] = hi;
    g_Wtp[l][1][n * TSTRIDE + k] = __float2bfloat16(lof);
}

// ---------------- parallel 3-phase exclusive scan -------------------------
__global__ void k_scan1() {
    __shared__ int swsum[32];
    int tid = threadIdx.x;
    int lane = tid & 31, wid = tid >> 5;
    int i = blockIdx.x * 1024 + tid;
    int x = (i < NN) ? g_deg[i] : 0;
#pragma unroll
    for (int off = 1; off < 32; off <<= 1) {
        int t = __shfl_up_sync(0xffffffffu, x, off);
        if (lane >= off) x += t;
    }
    if (lane == 31) swsum[wid] = x;
    __syncthreads();
    if (wid == 0) {
        int w = swsum[lane];
#pragma unroll
        for (int off = 1; off < 32; off <<= 1) {
            int t = __shfl_up_sync(0xffffffffu, w, off);
            if (lane >= off) w += t;
        }
        swsum[lane] = w;
    }
    __syncthreads();
    int incl = x + ((wid > 0) ? swsum[wid - 1] : 0);
    if (i < NN) g_rowptr[i + 1] = incl;
    if (tid == 1023) g_bsum[blockIdx.x] = incl;
    if (i == 0) g_rowptr[0] = 0;
}

__global__ void k_scan2() {
    __shared__ int s[128];
    int t = threadIdx.x;
    int v = (t < NSCAN) ? g_bsum[t] : 0;
    s[t] = v;
    __syncthreads();
#pragma unroll
    for (int off = 1; off < 128; off <<= 1) {
        int u = (t >= off) ? s[t - off] : 0;
        __syncthreads();
        s[t] += u;
        __syncthreads();
    }
    if (t < NSCAN) g_boff[t] = s[t] - v;
}

__global__ void k_scan3() {
    int i = blockIdx.x * blockDim.x + threadIdx.x;
    if (i < NN) g_rowptr[i + 1] += g_boff[i >> 10];
}

__global__ void k_scatter() {
    int e = blockIdx.x * blockDim.x + threadIdx.x;
    if (e >= EE) return;
    int s = g_src[e], d = g_dst[e];
    int p = atomicAdd(&g_cur[d], 1);
    int j = g_rowptr[d] + p;
    g_srcs[j] = s;
    g_pos[e] = j;
}

// ---------------- M2 fold: warp per output --------------------------------
__global__ void k_m2(const float* __restrict__ lin_e,
                     const float* __restrict__ att_e,
                     const float* __restrict__ efW,
                     const float* __restrict__ efb) {
    int out = blockIdx.x;
    int lane = threadIdx.x;
    float t = 0.f;
    if (out < 3 * EDIMC * 4) {
        int l = out / (EDIMC * 4), r = out % (EDIMC * 4);
        int k16 = r / 4, h = r % 4;
        for (int idx = lane; idx < 32 * 32; idx += 32) {
            int k32 = idx >> 5, c = idx & 31;
            t += efW[k16 * 32 + k32] *
                 lin_e[(size_t)l * 32 * HCC + k32 * HCC + h * 32 + c] *
                 att_e[l * HCC + h * 32 + c];
        }
#pragma unroll
        for (int off = 16; off > 0; off >>= 1)
            t += __shfl_down_sync(0xffffffffu, t, off);
        if (lane == 0) g_M2[l * (EDIMC * 4) + k16 * 4 + h] = t;
    } else {
        int j = out - 3 * EDIMC * 4;
        if (j >= 12) return;
        int l = j / 4, h = j % 4;
        for (int idx = lane; idx < 32 * 32; idx += 32) {
            int k32 = idx >> 5, c = idx & 31;
            t += efb[k32] *
                 lin_e[(size_t)l * 32 * HCC + k32 * HCC + h * 32 + c] *
                 att_e[l * HCC + h * 32 + c];
        }
#pragma unroll
        for (int off = 16; off > 0; off >>= 1)
            t += __shfl_down_sync(0xffffffffu, t, off);
        if (lane == 0) g_c2[l * 4 + h] = t;
    }
}

// ---------------- edge term for all 3 layers, written in CSR order --------
__global__ void k_e2(const float* __restrict__ ea) {
    __shared__ float sM[3 * EDIMC * 4];
    __shared__ float sc[12];
    if (threadIdx.x < 3 * EDIMC * 4) sM[threadIdx.x] = g_M2[threadIdx.x];
    if (threadIdx.x < 12) sc[threadIdx.x] = g_c2[threadIdx.x];
    __syncthreads();
    int e = blockIdx.x * blockDim.x + threadIdx.x;
    if (e >= EE) return;
    float ev[EDIMC];
    const float4* ep = (const float4*)(ea + (size_t)e * EDIMC);
#pragma unroll
    for (int q = 0; q < 4; q++) {
        float4 v = ep[q];
        ev[q * 4 + 0] = v.x; ev[q * 4 + 1] = v.y;
        ev[q * 4 + 2] = v.z; ev[q * 4 + 3] = v.w;
    }
    int p = g_pos[e];
#pragma unroll
    for (int l = 0; l < 3; l++) {
        float o[4];
#pragma unroll
        for (int h = 0; h < 4; h++) {
            float t = sc[l * 4 + h];
#pragma unroll
            for (int k = 0; k < EDIMC; k++)
                t += ev[k] * sM[l * 64 + k * 4 + h];
            o[h] = t;
        }
        ((float4*)g_e2)[(size_t)l * EE + p] = make_float4(o[0], o[1], o[2], o[3]);
    }
}

// ---------- bf16x3 split GEMM on mma.sync (+BN-on-load, +attn epilogue) ---
__device__ __forceinline__ void mma_bf16(float* c, uint32_t a0, uint32_t a1,
                                         uint32_t a2, uint32_t a3,
                                         uint32_t b0, uint32_t b1) {
    asm volatile(
        "mma.sync.aligned.m16n8k16.row.col.f32.bf16.bf16.f32 "
        "{%0,%1,%2,%3}, {%4,%5,%6,%7}, {%8,%9}, {%0,%1,%2,%3};"
        : "+f"(c[0]), "+f"(c[1]), "+f"(c[2]), "+f"(c[3])
        : "r"(a0), "r"(a1), "r"(a2), "r"(a3), "r"(b0), "r"(b1));
}

__global__ __launch_bounds__(256, 1)
void k_gemm_mma(const float* __restrict__ x_in, int use_x, int apply_bn, int l,
                const float* __restrict__ asl, const float* __restrict__ adl) {
    extern __shared__ __align__(16) unsigned char smem[];
    float* sAs = (float*)(smem + SAS_OFF);
    float* sAd = (float*)(smem + SAD_OFF);
    float* sScale = (float*)(smem + SSC_OFF);
    float* sShift = (float*)(smem + SSH_OFF);

    int tid = threadIdx.x;
    int w = tid >> 5, lane = tid & 31;
    int group = lane >> 2, tig = lane & 3;
    int row0 = blockIdx.x * 128;
    const float* A = use_x ? x_in : (const float*)g_B;

    if (tid < 128) {
        sAs[tid] = asl[tid];
        sAd[tid] = adl[tid];
        sScale[tid] = apply_bn ? g_bnscale[tid] : 1.f;
        sShift[tid] = apply_bn ? g_bnshift[tid] : 0.f;
    }
    // copy W^T hi+lo tiles (2 * 34816 B, contiguous in g_Wtp[l])
    {
        const uint4* src = (const uint4*)&g_Wtp[l][0][0];
        uint4* dst = (uint4*)(smem + BH_OFF);
        int n16 = 2 * TBYTES / 16;   // 4352
        for (int i = tid; i < n16; i += 256) dst[i] = src[i];
    }
    __syncthreads();

    // load A tile, BN+ReLU, split hi/lo
#pragma unroll
    for (int i = 0; i < 16; i++) {
        int idx = tid + i * 256;     // 0..4095
        int r = idx >> 5, q = idx & 31;
        int gr = row0 + r;
        float4 v = (gr < NN) ? ((const float4*)(A + (size_t)gr * HCC))[q]
                             : make_float4(0.f, 0.f, 0.f, 0.f);
        if (apply_bn) {
            int c = q * 4;
            v.x = fmaxf(v.x * sScale[c + 0] + sShift[c + 0], 0.f);
            v.y = fmaxf(v.y * sScale[c + 1] + sShift[c + 1], 0.f);
            v.z = fmaxf(v.z * sScale[c + 2] + sShift[c + 2], 0.f);
            v.w = fmaxf(v.w * sScale[c + 3] + sShift[c + 3], 0.f);
        }
        unsigned short h0 = __bfloat16_as_ushort(__float2bfloat16(v.x));
        unsigned short h1 = __bfloat16_as_ushort(__float2bfloat16(v.y));
        unsigned short h2 = __bfloat16_as_ushort(__float2bfloat16(v.z));
        unsigned short h3 = __bfloat16_as_ushort(__float2bfloat16(v.w));
        float l0 = v.x - __bfloat162float(__ushort_as_bfloat16(h0));
        float l1 = v.y - __bfloat162float(__ushort_as_bfloat16(h1));
        float l2 = v.z - __bfloat162float(__ushort_as_bfloat16(h2));
        float l3 = v.w - __bfloat162float(__ushort_as_bfloat16(h3));
        uint2 hp = make_uint2((uint32_t)h0 | ((uint32_t)h1 << 16),
                              (uint32_t)h2 | ((uint32_t)h3 << 16));
        uint2 lp = make_uint2(
            (uint32_t)__bfloat16_as_ushort(__float2bfloat16(l0)) |
                ((uint32_t)__bfloat16_as_ushort(__float2bfloat16(l1)) << 16),
            (uint32_t)__bfloat16_as_ushort(__float2bfloat16(l2)) |
                ((uint32_t)__bfloat16_as_ushort(__float2bfloat16(l3)) << 16));
        uint32_t off = (uint32_t)r * (TSTRIDE * 2) + (uint32_t)q * 8;
        *(uint2*)(smem + AH_OFF + off) = hp;
        *(uint2*)(smem + AL_OFF + off) = lp;
    }
    __syncthreads();

    float acc[64];
#pragma unroll
    for (int i = 0; i < 64; i++) acc[i] = 0.f;

    const unsigned char* Aprod[3] = {smem + AH_OFF, smem + AH_OFF, smem + AL_OFF};
    const unsigned char* Bprod[3] = {smem + BH_OFF, smem + BL_OFF, smem + BH_OFF};
    uint32_t arow0 = (uint32_t)(w * 16 + group) * (TSTRIDE * 2);
    uint32_t arow1 = arow0 + 8 * (TSTRIDE * 2);

#pragma unroll
    for (int prod = 0; prod < 3; prod++) {
        const unsigned char* Ab = Aprod[prod];
        const unsigned char* Bb = Bprod[prod];
#pragma unroll
        for (int kc = 0; kc < 8; kc++) {
            uint32_t ka = (uint32_t)kc * 32 + (uint32_t)tig * 4;
            uint32_t a0 = *(const uint32_t*)(Ab + arow0 + ka);
            uint32_t a1 = *(const uint32_t*)(Ab + arow1 + ka);
            uint32_t a2 = *(const uint32_t*)(Ab + arow0 + ka + 16);
            uint32_t a3 = *(const uint32_t*)(Ab + arow1 + ka + 16);
#pragma unroll
            for (int nt = 0; nt < 16; nt++) {
                uint32_t brow = (uint32_t)(nt * 8 + group) * (TSTRIDE * 2);
                uint32_t b0 = *(const uint32_t*)(Bb + brow + ka);
                uint32_t b1 = *(const uint32_t*)(Bb + brow + ka + 16);
                mma_bf16(acc + nt * 4, a0, a1, a2, a3, b0, b1);
            }
        }
    }

    // epilogue: per-head attn partials + C stores
    int rA = row0 + w * 16 + group;
    int rB = rA + 8;
    float ps0[4] = {0, 0, 0, 0}, pd0[4] = {0, 0, 0, 0};
    float ps1[4] = {0, 0, 0, 0}, pd1[4] = {0, 0, 0, 0};
#pragma unroll
    for (int nt = 0; nt < 16; nt++) {
        int h = nt >> 2;
        int c = nt * 8 + tig * 2;
        float a0 = acc[nt * 4 + 0], a1 = acc[nt * 4 + 1];
        float a2 = acc[nt * 4 + 2], a3 = acc[nt * 4 + 3];
        ps0[h] += a0 * sAs[c] + a1 * sAs[c + 1];
        pd0[h] += a0 * sAd[c] + a1 * sAd[c + 1];
        ps1[h] += a2 * sAs[c] + a3 * sAs[c + 1];
        pd1[h] += a2 * sAd[c] + a3 * sAd[c + 1];
        if (rA < NN)
            *(float2*)(g_A + (size_t)rA * HCC + c) = make_float2(a0, a1);
        if (rB < NN)
            *(float2*)(g_A + (size_t)rB * HCC + c) = make_float2(a2, a3);
    }
#pragma unroll
    for (int off = 1; off < 4; off <<= 1) {
#pragma unroll
        for (int h = 0; h < 4; h++) {
            ps0[h] += __shfl_xor_sync(0xffffffffu, ps0[h], off, 4);
            pd0[h] += __shfl_xor_sync(0xffffffffu, pd0[h], off, 4);
            ps1[h] += __shfl_xor_sync(0xffffffffu, ps1[h], off, 4);
            pd1[h] += __shfl_xor_sync(0xffffffffu, pd1[h], off, 4);
        }
    }
    if (rA < NN) {
        g_asrc[rA * 4 + tig] = ps0[tig];
        g_adst[rA * 4 + tig] = pd0[tig];
    }
    if (rB < NN) {
        g_asrc[rB * 4 + tig] = ps1[tig];
        g_adst[rB * 4 + tig] = pd1[tig];
    }
}

// -------- fused edge-weight + atomic-free aggregate: warp per node --------
__global__ __launch_bounds__(256)
void k_agg(int l) {
    int node = (blockIdx.x * blockDim.x + threadIdx.x) >> 5;
    int lane = threadIdx.x & 31;
    if (node >= NN) return;
    int start = g_rowptr[node], end = g_rowptr[node + 1];

    float4 ad = ((const float4*)g_adst)[node];
    float4 ds = make_float4(0.f, 0.f, 0.f, 0.f);
    for (int j = start + lane; j < end; j += 32) {
        int s = g_srcs[j];
        float4 as = ((const float4*)g_asrc)[s];
        float4 e2 = ((const float4*)g_e2)[(size_t)l * EE + j];
        float a0 = as.x + ad.x + e2.x;
        float a1 = as.y + ad.y + e2.y;
        float a2 = as.z + ad.z + e2.z;
        float a3 = as.w + ad.w + e2.w;
        a0 = (a0 > 0.f) ? a0 : SLOPE * a0;
        a1 = (a1 > 0.f) ? a1 : SLOPE * a1;
        a2 = (a2 > 0.f) ? a2 : SLOPE * a2;
        a3 = (a3 > 0.f) ? a3 : SLOPE * a3;
        float4 w = make_float4(__expf(a0), __expf(a1), __expf(a2), __expf(a3));
        ((float4*)g_alpha)[j] = w;
        ds.x += w.x; ds.y += w.y; ds.z += w.z; ds.w += w.w;
    }
    __syncwarp();
#pragma unroll
    for (int off = 16; off > 0; off >>= 1) {
        ds.x += __shfl_xor_sync(0xffffffffu, ds.x, off);
        ds.y += __shfl_xor_sync(0xffffffffu, ds.y, off);
        ds.z += __shfl_xor_sync(0xffffffffu, ds.z, off);
        ds.w += __shfl_xor_sync(0xffffffffu, ds.w, off);
    }
    int h = lane >> 3;
    float dh = (h == 0) ? ds.x : (h == 1) ? ds.y : (h == 2) ? ds.z : ds.w;
    float inv = 1.f / (dh + 1e-16f);

    float4 acc = make_float4(0.f, 0.f, 0.f, 0.f);
    for (int j = start; j < end; j++) {
        int s = g_srcs[j];
        float coef = g_alpha[(size_t)j * 4 + h] * inv;
        float4 v = ((const float4*)(g_A + (size_t)s * HCC))[lane];
        acc.x += coef * v.x; acc.y += coef * v.y;
        acc.z += coef * v.z; acc.w += coef * v.w;
    }
    ((float4*)(g_B + (size_t)node * HCC))[lane] = acc;
}

// ---------------- batch-norm stats (atomic-free partials) ------------------
__global__ void k_bnstat() {
    int c = threadIdx.x;
    double s = 0.0, q = 0.0;
    for (int r = blockIdx.x; r < NN; r += 512) {
        float v = g_B[(size_t)r * HCC + c];
        s += v;
        q += (double)v * v;
    }
    g_bnS[blockIdx.x * HCC + c] = s;
    g_bnQ[blockIdx.x * HCC + c] = q;
}

__global__ void k_bnfinal(const float* __restrict__ gamma,
                          const float* __restrict__ beta) {
    __shared__ double ss[256], sq[256];
    int c = blockIdx.x;
    int t = threadIdx.x;
    double s = g_bnS[t * HCC + c] + g_bnS[(t + 256) * HCC + c];
    double q = g_bnQ[t * HCC + c] + g_bnQ[(t + 256) * HCC + c];
    ss[t] = s; sq[t] = q;
    __syncthreads();
#pragma unroll
    for (int off = 128; off > 0; off >>= 1) {
        if (t < off) { ss[t] += ss[t + off]; sq[t] += sq[t + off]; }
        __syncthreads();
    }
    if (t == 0) {
        float mu = (float)(ss[0] / (double)NN);
        float var = (float)(sq[0] / (double)NN) - mu * mu;
        float rstd = rsqrtf(var + BN_EPS);
        float sc = rstd * gamma[c];
        g_bnscale[c] = sc;
        g_bnshift[c] = beta[c] - mu * sc;
    }
}

// ---------------- pooling (applies last BN+ReLU) + final FC ----------------
__global__ void k_pool() {
    int i = blockIdx.x * blockDim.x + threadIdx.x;
    if (i >= NN * 32) return;
    int n = i >> 5, q = i & 31;
    int g = g_batch[n];
    int c = q * 4;
    float4 v = ((const float4*)(g_B + (size_t)n * HCC))[q];
    v.x = fmaxf(v.x * g_bnscale[c + 0] + g_bnshift[c + 0], 0.f);
    v.y = fmaxf(v.y * g_bnscale[c + 1] + g_bnshift[c + 1], 0.f);
    v.z = fmaxf(v.z * g_bnscale[c + 2] + g_bnshift[c + 2], 0.f);
    v.w = fmaxf(v.w * g_bnscale[c + 3] + g_bnshift[c + 3], 0.f);
    atomicAdd(((float4*)(g_pool + (size_t)g * HCC)) + q, v);
}

__global__ void k_fc(const float* __restrict__ fcW,
                     const float* __restrict__ fcb,
                     float* __restrict__ out) {
    int g = threadIdx.x;
    if (g >= GG) return;
    float inv = 1.f / fmaxf(g_cnt[g], 1.f);
    float o0 = fcb[0], o1 = fcb[1];
    for (int c = 0; c < HCC; c++) {
        float p = g_pool[(size_t)g * HCC + c] * inv;
        o0 += p * fcW[c * 2 + 0];
        o1 += p * fcW[c * 2 + 1];
    }
    out[g * 2 + 0] = o0;
    out[g * 2 + 1] = o1;
}

// ---------------- launch ----------------------------------------------------
extern "C" void kernel_launch(void* const* d_in, const int* in_sizes, int n_in,
                              void* d_out, int out_size) {
    const float* x     = (const float*)d_in[0];
    const void*  ei    = d_in[1];
    const float* ea    = (const float*)d_in[2];
    const void*  batch = d_in[3];
    const float* efW   = (const float*)d_in[4];
    const float* efb   = (const float*)d_in[5];
    const float* Ws    = (const float*)d_in[6];
    const float* a_s   = (const float*)d_in[7];
    const float* a_d   = (const float*)d_in[8];
    const float* a_e   = (const float*)d_in[9];
    const float* lin_e = (const float*)d_in[10];
    const float* gamma = (const float*)d_in[12];
    const float* beta  = (const float*)d_in[13];
    const float* fcW   = (const float*)d_in[14];
    const float* fcb   = (const float*)d_in[15];
    float* out = (float*)d_out;

    static int smem_set = 0;
    if (!smem_set) {
        cudaFuncSetAttribute(k_gemm_mma,
                             cudaFuncAttributeMaxDynamicSharedMemorySize,
                             SMEM_MM);
        smem_set = 1;
    }

    k_detect<<<1, 32>>>((const int*)ei);
    k_init<<<(NN + 255) / 256, 256>>>();
    k_prep<<<(EE + 255) / 256, 256>>>(ei, batch);
    k_wprep<<<192, 256>>>(Ws);
    k_scan1<<<NSCAN, 1024>>>();
    k_scan2<<<1, 128>>>();
    k_scan3<<<(NN + 1023) / 1024, 1024>>>();
    k_scatter<<<(EE + 255) / 256, 256>>>();
    k_m2<<<3 * EDIMC * 4 + 12, 32>>>(lin_e, a_e, efW, efb);
    k_e2<<<(EE + 255) / 256, 256>>>(ea);

    for (int l = 0; l < 3; l++) {
        k_gemm_mma<<<(NN + 127) / 128, 256, SMEM_MM>>>(
            x, (l == 0) ? 1 : 0, (l == 0) ? 0 : 1, l,
            a_s + l * HCC, a_d + l * HCC);
        k_agg<<<(NN * 32 + 255) / 256, 256>>>(l);
        k_bnstat<<<512, 128>>>();
        k_bnfinal<<<128, 256>>>(gamma + l * HCC, beta + l * HCC);
    }

    k_pool<<<(NN * 32 + 255) / 256, 256>>>();
    k_fc<<<1, 256>>>(fcW, fcb, out);
}